// round 3
// baseline (speedup 1.0000x reference)
#include <cuda_runtime.h>
#include <cuda_bf16.h>
#include <mma.h>
#include <cstdint>

using namespace nvcuda;

#define H      1024
#define H2     2048
#define VOCAB  32001
#define DEPTH  11
#define NODES  4095   // 2^12 - 1

// ---------------- scratch (static device globals: allowed) ----------------
__device__ __nv_bfloat16 g_h[NODES * H];      // all node hiddens, bf16, BFS order
__device__ __nv_bfloat16 g_mid[NODES * H2];   // sigmoid activations (reused per level, then full for vocab)

// ---------------- GEMM tile config ----------------
constexpr int BM = 128;
constexpr int BN = 64;
constexpr int BK = 32;
constexpr int LDA_S = BK + 8;   // 40 elems (80B rows, 16B aligned)
constexpr int LDB_S = BN + 8;   // 72 elems (144B rows, 16B aligned)

// pre-order index of BFS node j (perfect binary tree, levels 0..DEPTH)
__device__ __forceinline__ int preorder_row(int j) {
    int t = j + 1;
    int d = 31 - __clz(t);          // depth
    int p = t - (1 << d);           // position within level
    int idx = 0;
    #pragma unroll 1
    for (int k = 0; k < d; ++k) {
        int b = (p >> (d - 1 - k)) & 1;
        idx += 1 + b * ((1 << (DEPTH - k)) - 1);   // skip left subtree if going right
    }
    return idx;
}

// MODE 0: out = bf16(sigmoid(acc+bias)), row-major ld=N  (outp = bf16 buffer)
// MODE 1: child scatter: node = child_off + 2*m + (n>>10), col = n&1023 -> g_h
// MODE 2: logits: row = preorder(m), fp32 -> outp (d_out), ld = VOCAB
template <int MODE>
__global__ void __launch_bounds__(256)
gemm_kernel(const __nv_bfloat16* __restrict__ A, int lda,
            const float* __restrict__ B, int ldb,
            const float* __restrict__ bias,
            int M, int N, int K,
            void* outp, int child_off)
{
    __shared__ __nv_bfloat16 As[BM * LDA_S];
    __shared__ __nv_bfloat16 Bs[BK * LDB_S];
    __shared__ float         Cs[BM * BN];

    const int tid  = threadIdx.x;
    const int warp = tid >> 5;
    const int wm   = warp & 3;   // warp M index (0..3), 32 rows each
    const int wn   = warp >> 2;  // warp N index (0..1), 32 cols each
    const int m0   = blockIdx.x * BM;
    const int n0   = blockIdx.y * BN;

    wmma::fragment<wmma::accumulator, 16, 16, 16, float> acc[2][2];
    #pragma unroll
    for (int i = 0; i < 2; ++i)
        #pragma unroll
        for (int j = 0; j < 2; ++j)
            wmma::fill_fragment(acc[i][j], 0.0f);

    // A load map: 256 threads -> 128 rows x 2 segments of 16 bf16 (32B)
    const int arow = tid >> 1;
    const int aseg = (tid & 1) * 16;
    // B load map: 256 threads -> 32 rows x 8 groups of 8 floats
    const int brow = tid >> 3;
    const int bc0  = (tid & 7) * 8;

    for (int k0 = 0; k0 < K; k0 += BK) {
        // ---- load A tile (bf16, vectorized 2x float4) ----
        {
            float4 v0 = make_float4(0.f, 0.f, 0.f, 0.f);
            float4 v1 = v0;
            const int gm = m0 + arow;
            if (gm < M) {
                const float4* src = reinterpret_cast<const float4*>(
                    A + (size_t)gm * lda + k0 + aseg);
                v0 = src[0];
                v1 = src[1];
            }
            float4* dst = reinterpret_cast<float4*>(&As[arow * LDA_S + aseg]);
            dst[0] = v0;
            dst[1] = v1;
        }
        // ---- load B tile (fp32 -> bf16 convert) ----
        {
            const int gk = k0 + brow;   // always < K (K multiple of 32)
            const float* src = B + (size_t)gk * ldb + n0 + bc0;
            __nv_bfloat16* dst = &Bs[brow * LDB_S + bc0];
            #pragma unroll
            for (int c = 0; c < 8; ++c) {
                float v = (n0 + bc0 + c < N) ? src[c] : 0.0f;
                dst[c] = __float2bfloat16(v);
            }
        }
        __syncthreads();

        #pragma unroll
        for (int kk = 0; kk < BK; kk += 16) {
            wmma::fragment<wmma::matrix_a, 16, 16, 16, __nv_bfloat16, wmma::row_major> af[2];
            wmma::fragment<wmma::matrix_b, 16, 16, 16, __nv_bfloat16, wmma::row_major> bf[2];
            #pragma unroll
            for (int i = 0; i < 2; ++i)
                wmma::load_matrix_sync(af[i], &As[(wm * 32 + i * 16) * LDA_S + kk], LDA_S);
            #pragma unroll
            for (int j = 0; j < 2; ++j)
                wmma::load_matrix_sync(bf[j], &Bs[kk * LDB_S + wn * 32 + j * 16], LDB_S);
            #pragma unroll
            for (int i = 0; i < 2; ++i)
                #pragma unroll
                for (int j = 0; j < 2; ++j)
                    wmma::mma_sync(acc[i][j], af[i], bf[j], acc[i][j]);
        }
        __syncthreads();
    }

    // ---- stage accumulators to shared, then predicated epilogue ----
    #pragma unroll
    for (int i = 0; i < 2; ++i)
        #pragma unroll
        for (int j = 0; j < 2; ++j)
            wmma::store_matrix_sync(&Cs[(wm * 32 + i * 16) * BN + wn * 32 + j * 16],
                                    acc[i][j], BN, wmma::mem_row_major);
    __syncthreads();

    for (int idx = tid; idx < BM * BN; idx += 256) {
        const int r = idx / BN, c = idx % BN;
        const int m = m0 + r, n = n0 + c;
        if (m >= M || n >= N) continue;
        float v = Cs[idx] + bias[n];
        if (MODE == 0) {
            v = 1.0f / (1.0f + __expf(-v));
            ((__nv_bfloat16*)outp)[(size_t)m * N + n] = __float2bfloat16(v);
        } else if (MODE == 1) {
            const int node = child_off + 2 * m + (n >> 10);
            const int col  = n & (H - 1);
            g_h[(size_t)node * H + col] = __float2bfloat16(v);
        } else { // MODE == 2
            const int prow = preorder_row(m);
            ((float*)outp)[(size_t)prow * VOCAB + n] = v;
        }
    }
}

__global__ void cvt_root_kernel(const float* __restrict__ root) {
    int i = blockIdx.x * 256 + threadIdx.x;
    if (i < H) g_h[i] = __float2bfloat16(root[i]);
}

__global__ void __launch_bounds__(256)
logsoftmax_kernel(float* __restrict__ out) {
    const size_t row = blockIdx.x;
    float* p = out + row * (size_t)VOCAB;
    __shared__ float red[8];
    __shared__ float s_val;
    const int tid = threadIdx.x;

    // pass 1: max
    float mx = -1e30f;
    for (int i = tid; i < VOCAB; i += 256) mx = fmaxf(mx, p[i]);
    #pragma unroll
    for (int o = 16; o; o >>= 1) mx = fmaxf(mx, __shfl_xor_sync(0xffffffffu, mx, o));
    if ((tid & 31) == 0) red[tid >> 5] = mx;
    __syncthreads();
    if (tid < 8) {
        mx = red[tid];
        #pragma unroll
        for (int o = 4; o; o >>= 1) mx = fmaxf(mx, __shfl_xor_sync(0xffu, mx, o));
        if (tid == 0) s_val = mx;
    }
    __syncthreads();
    mx = s_val;

    // pass 2: sum exp
    float sum = 0.0f;
    for (int i = tid; i < VOCAB; i += 256) sum += __expf(p[i] - mx);
    #pragma unroll
    for (int o = 16; o; o >>= 1) sum += __shfl_xor_sync(0xffffffffu, sum, o);
    __syncthreads();
    if ((tid & 31) == 0) red[tid >> 5] = sum;
    __syncthreads();
    if (tid < 8) {
        sum = red[tid];
        #pragma unroll
        for (int o = 4; o; o >>= 1) sum += __shfl_xor_sync(0xffu, sum, o);
        if (tid == 0) s_val = mx + logf(sum);
    }
    __syncthreads();
    const float lse = s_val;

    // pass 3: write
    for (int i = tid; i < VOCAB; i += 256) p[i] -= lse;
}

extern "C" void kernel_launch(void* const* d_in, const int* in_sizes, int n_in,
                              void* d_out, int out_size) {
    (void)in_sizes; (void)n_in; (void)out_size;
    const float* root = (const float*)d_in[0];
    const float* W1v  = (const float*)d_in[1];
    const float* b1v  = (const float*)d_in[2];
    const float* W2v  = (const float*)d_in[3];
    const float* b2v  = (const float*)d_in[4];
    const float* W1c  = (const float*)d_in[5];
    const float* b1c  = (const float*)d_in[6];
    const float* W2c  = (const float*)d_in[7];
    const float* b2c  = (const float*)d_in[8];

    void *g_h_addr = nullptr, *g_mid_addr = nullptr;
    cudaGetSymbolAddress(&g_h_addr, g_h);
    cudaGetSymbolAddress(&g_mid_addr, g_mid);
    __nv_bfloat16* g_h_p   = (__nv_bfloat16*)g_h_addr;
    __nv_bfloat16* g_mid_p = (__nv_bfloat16*)g_mid_addr;

    cvt_root_kernel<<<4, 256>>>(root);

    // ---- tree expansion: level d (2^d nodes at BFS offset 2^d-1) -> level d+1 ----
    int off = 0;                       // 2^d - 1
    for (int d = 0; d < DEPTH; ++d) {
        const int R = 1 << d;
        dim3 grid((R + BM - 1) / BM, (H2 + BN - 1) / BN);
        // mid = sigmoid(h_level @ W1c + b1c)
        gemm_kernel<0><<<grid, 256>>>(g_h_p + (size_t)off * H, H,
                                      W1c, H2, b1c, R, H2, H, g_mid_p, 0);
        // children = mid @ W2c + b2c, scattered into g_h at level d+1
        gemm_kernel<1><<<grid, 256>>>(g_mid_p, H2,
                                      W2c, H2, b2c, R, H2, H2, nullptr, 2 * off + 1);
        off = 2 * off + 1;
    }

    // ---- vocab first layer for ALL nodes: midv = sigmoid(g_h @ W1v + b1v) ----
    {
        dim3 grid((NODES + BM - 1) / BM, (H2 + BN - 1) / BN);
        gemm_kernel<0><<<grid, 256>>>(g_h_p, H, W1v, H2, b1v,
                                      NODES, H2, H, g_mid_p, 0);
    }

    // ---- big logits GEMM: [4095,2048] x [2048,32001], pre-order permuted rows ----
    {
        // x = M-tiles (fastest): consecutive CTAs share the same B N-strip -> L2 reuse
        dim3 grid((NODES + BM - 1) / BM, (VOCAB + BN - 1) / BN);
        gemm_kernel<2><<<grid, 256>>>(g_mid_p, H2, W2v, VOCAB, b2v,
                                      NODES, VOCAB, H2, d_out, 0);
    }

    // ---- in-place log-softmax per row ----
    logsoftmax_kernel<<<NODES, 256>>>((float*)d_out);
}

// round 4
// speedup vs baseline: 2.0139x; 2.0139x over previous
#include <cuda_runtime.h>
#include <cuda_bf16.h>
#include <cstdint>

#define H      1024
#define H2     2048
#define VOCAB  32001
#define VPAD   32128   // 251 * 128, padded bf16 W2v so all tile loads are in-bounds
#define DEPTH  11
#define NODES  4095

// ---------------- scratch (static device globals: allowed) ----------------
__device__ __nv_bfloat16 g_h[NODES * H];                 // node hiddens, BFS order
__device__ __nv_bfloat16 g_mid[(size_t)NODES * H2];      // sigmoid activations
__device__ __nv_bfloat16 g_W1c[H * H2];
__device__ __nv_bfloat16 g_W2c[H2 * H2];
__device__ __nv_bfloat16 g_W1v[H * H2];
__device__ __nv_bfloat16 g_W2v[(size_t)H2 * VPAD];       // zero-padded cols [32001,32128)

// ---------------- tile config ----------------
constexpr int BM = 128;
constexpr int BN = 128;
constexpr int BK = 32;
constexpr int STAGES = 3;
// A stage: 128 rows x 64B (BK bf16)  = 8192B
// B stage: 32 rows  x 256B (BN bf16) = 8192B
// 3*(8192+8192) = 49152B = exactly the 48KB static smem limit

__device__ __forceinline__ uint32_t smem_u32(const void* p) {
    return (uint32_t)__cvta_generic_to_shared(p);
}

// pre-order position of BFS node j (perfect binary tree, levels 0..DEPTH)
__device__ __forceinline__ int preorder_row(int j) {
    int t = j + 1;
    int d = 31 - __clz(t);
    int p = t - (1 << d);
    int idx = 0;
    #pragma unroll 1
    for (int k = 0; k < d; ++k) {
        int b = (p >> (d - 1 - k)) & 1;
        idx += 1 + b * ((1 << (DEPTH - k)) - 1);
    }
    return idx;
}

// MODE 0: out = bf16(sigmoid(acc+bias)) -> (bf16*)outp, ld = N
// MODE 1: child scatter -> g_h : node = child_off + 2*m + (n>>10), col = n&1023
// MODE 2: logits fp32 -> (float*)outp at row preorder_row(m), ld = VOCAB
template <int MODE>
__global__ void __launch_bounds__(256, 2)
gemm_bf16(const __nv_bfloat16* __restrict__ A, int lda,
          const __nv_bfloat16* __restrict__ B, int ldb,
          const float* __restrict__ bias,
          int M, int N, int K,
          void* outp, int child_off)
{
    __shared__ __align__(16) unsigned char smem[STAGES * 2 * 8192];

    const int tid  = threadIdx.x;
    const int wid  = tid >> 5;
    const int lane = tid & 31;
    const int wm   = wid & 3;     // 0..3 : 32-row strip
    const int wn   = wid >> 2;    // 0..1 : 64-col strip
    const int m0   = blockIdx.x * BM;
    const int n0   = blockIdx.y * BN;

    const uint32_t sA = smem_u32(smem);
    const uint32_t sB = sA + STAGES * 8192;

    float acc[2][8][4];
    #pragma unroll
    for (int i = 0; i < 2; ++i)
        #pragma unroll
        for (int j = 0; j < 8; ++j)
            #pragma unroll
            for (int q = 0; q < 4; ++q) acc[i][j][q] = 0.0f;

    auto load_stage = [&](int s, int k0) {
        // A: 512 chunks of 16B (row = q>>2, c = q&3), swizzle c ^= (row>>1)&3
        #pragma unroll
        for (int t = 0; t < 2; ++t) {
            int q = tid + t * 256;
            int r = q >> 2, c = q & 3;
            uint32_t dst = sA + s * 8192 + r * 64 + ((c ^ ((r >> 1) & 3)) << 4);
            int gm = m0 + r;
            int sz = (gm < M) ? 16 : 0;
            if (gm >= M) gm = M - 1;                    // keep address valid
            const __nv_bfloat16* src = A + (size_t)gm * lda + k0 + c * 8;
            asm volatile("cp.async.cg.shared.global [%0], [%1], 16, %2;\n"
                         :: "r"(dst), "l"(src), "r"(sz));
        }
        // B: 512 chunks (k = q>>4, nc = q&15), swizzle nc ^= k&7. Always in-bounds (padded).
        #pragma unroll
        for (int t = 0; t < 2; ++t) {
            int q = tid + t * 256;
            int k = q >> 4, nc = q & 15;
            uint32_t dst = sB + s * 8192 + k * 256 + ((nc ^ (k & 7)) << 4);
            const __nv_bfloat16* src = B + (size_t)(k0 + k) * ldb + n0 + nc * 8;
            asm volatile("cp.async.cg.shared.global [%0], [%1], 16;\n"
                         :: "r"(dst), "l"(src));
        }
    };

    const int kiters = K >> 5;

    #pragma unroll
    for (int s = 0; s < STAGES - 1; ++s) {
        load_stage(s, s * BK);
        asm volatile("cp.async.commit_group;\n");
    }

    for (int it = 0; it < kiters; ++it) {
        asm volatile("cp.async.wait_group %0;\n" :: "n"(STAGES - 2));
        __syncthreads();
        {
            int pf = it + STAGES - 1;
            if (pf < kiters) load_stage(pf % STAGES, pf * BK);
            asm volatile("cp.async.commit_group;\n");
        }
        const uint32_t aBase = sA + (it % STAGES) * 8192;
        const uint32_t bBase = sB + (it % STAGES) * 8192;

        #pragma unroll
        for (int kk = 0; kk < 2; ++kk) {          // two k16 steps per BK=32
            uint32_t a[2][4];
            #pragma unroll
            for (int i = 0; i < 2; ++i) {
                int r = wm * 32 + i * 16 + (lane & 15);
                int c = kk * 2 + (lane >> 4);
                uint32_t addr = aBase + r * 64 + ((c ^ ((r >> 1) & 3)) << 4);
                asm volatile("ldmatrix.sync.aligned.m8n8.x4.shared.b16 {%0,%1,%2,%3}, [%4];\n"
                             : "=r"(a[i][0]), "=r"(a[i][1]), "=r"(a[i][2]), "=r"(a[i][3])
                             : "r"(addr));
            }
            #pragma unroll
            for (int j2 = 0; j2 < 4; ++j2) {      // each covers 16 cols = 2 n-frags
                uint32_t b[4];
                int k  = kk * 16 + (lane & 15);
                int nc = wn * 8 + j2 * 2 + (lane >> 4);
                uint32_t addr = bBase + k * 256 + ((nc ^ (k & 7)) << 4);
                asm volatile("ldmatrix.sync.aligned.m8n8.x4.trans.shared.b16 {%0,%1,%2,%3}, [%4];\n"
                             : "=r"(b[0]), "=r"(b[1]), "=r"(b[2]), "=r"(b[3])
                             : "r"(addr));
                #pragma unroll
                for (int jj = 0; jj < 2; ++jj) {
                    int j = j2 * 2 + jj;
                    #pragma unroll
                    for (int i = 0; i < 2; ++i) {
                        asm volatile(
                            "mma.sync.aligned.m16n8k16.row.col.f32.bf16.bf16.f32 "
                            "{%0,%1,%2,%3}, {%4,%5,%6,%7}, {%8,%9}, {%0,%1,%2,%3};\n"
                            : "+f"(acc[i][j][0]), "+f"(acc[i][j][1]),
                              "+f"(acc[i][j][2]), "+f"(acc[i][j][3])
                            : "r"(a[i][0]), "r"(a[i][1]), "r"(a[i][2]), "r"(a[i][3]),
                              "r"(b[jj * 2]), "r"(b[jj * 2 + 1]));
                    }
                }
            }
        }
    }

    // ---- epilogue straight from registers ----
    // acc frag map: c0,c1 -> (row r0, cols cc,cc+1); c2,c3 -> (row r0+8, same cols)
    const int r0 = lane >> 2;
    const int cc = (lane & 3) * 2;
    #pragma unroll
    for (int i = 0; i < 2; ++i) {
        const int mbase = m0 + wm * 32 + i * 16;
        const int mA = mbase + r0;
        const int mB = mbase + r0 + 8;
        int prA = 0, prB = 0;
        if (MODE == 2) {
            if (mA < M) prA = preorder_row(mA);
            if (mB < M) prB = preorder_row(mB);
        }
        #pragma unroll
        for (int j = 0; j < 8; ++j) {
            const int n = n0 + wn * 64 + j * 8 + cc;
            float bv0, bv1;
            if (MODE == 2) {
                bv0 = (n     < N) ? bias[n]     : 0.0f;
                bv1 = (n + 1 < N) ? bias[n + 1] : 0.0f;
            } else {
                float2 bb = *(const float2*)(bias + n);
                bv0 = bb.x; bv1 = bb.y;
            }
            float v0 = acc[i][j][0] + bv0, v1 = acc[i][j][1] + bv1;
            float v2 = acc[i][j][2] + bv0, v3 = acc[i][j][3] + bv1;

            if (MODE == 0) {
                v0 = 1.0f / (1.0f + __expf(-v0));
                v1 = 1.0f / (1.0f + __expf(-v1));
                v2 = 1.0f / (1.0f + __expf(-v2));
                v3 = 1.0f / (1.0f + __expf(-v3));
                __nv_bfloat16* O = (__nv_bfloat16*)outp;
                if (mA < M) *(__nv_bfloat162*)(O + (size_t)mA * N + n) =
                    __nv_bfloat162(__float2bfloat16(v0), __float2bfloat16(v1));
                if (mB < M) *(__nv_bfloat162*)(O + (size_t)mB * N + n) =
                    __nv_bfloat162(__float2bfloat16(v2), __float2bfloat16(v3));
            } else if (MODE == 1) {
                const int nodeb = child_off + (n >> 10);
                const int col   = n & (H - 1);
                if (mA < M) *(__nv_bfloat162*)&g_h[(size_t)(nodeb + 2 * mA) * H + col] =
                    __nv_bfloat162(__float2bfloat16(v0), __float2bfloat16(v1));
                if (mB < M) *(__nv_bfloat162*)&g_h[(size_t)(nodeb + 2 * mB) * H + col] =
                    __nv_bfloat162(__float2bfloat16(v2), __float2bfloat16(v3));
            } else {
                float* O = (float*)outp;   // rows are 32001 floats -> only 4B aligned: scalar stores
                if (mA < M) {
                    if (n     < N) O[(size_t)prA * VOCAB + n]     = v0;
                    if (n + 1 < N) O[(size_t)prA * VOCAB + n + 1] = v1;
                }
                if (mB < M) {
                    if (n     < N) O[(size_t)prB * VOCAB + n]     = v2;
                    if (n + 1 < N) O[(size_t)prB * VOCAB + n + 1] = v3;
                }
            }
        }
    }
}

// ---------------- converts ----------------
__global__ void cvt_root_kernel(const float* __restrict__ root) {
    int i = blockIdx.x * 256 + threadIdx.x;
    if (i < H) g_h[i] = __float2bfloat16(root[i]);
}

__global__ void cvt_w_kernel(const float* __restrict__ src, __nv_bfloat16* __restrict__ dst, int n) {
    int i = blockIdx.x * 256 + threadIdx.x;
    if (i < n) dst[i] = __float2bfloat16(src[i]);
}

__global__ void cvt_pad_kernel(const float* __restrict__ src, __nv_bfloat16* __restrict__ dst,
                               int nc, int ncp, int total) {
    int i = blockIdx.x * 256 + threadIdx.x;
    if (i < total) {
        int r = i / ncp, c = i - r * ncp;
        dst[i] = (c < nc) ? __float2bfloat16(src[(size_t)r * nc + c]) : __float2bfloat16(0.0f);
    }
}

// ---------------- online log-softmax (2 passes over gmem) ----------------
__global__ void __launch_bounds__(256)
logsoftmax_kernel(float* __restrict__ out) {
    float* p = out + blockIdx.x * (size_t)VOCAB;
    const int tid = threadIdx.x;
    __shared__ float sm[8], ss[8];
    __shared__ float s_lse;

    float m = -1e30f, s = 0.0f;
    for (int i = tid; i < VOCAB; i += 256) {
        float x = p[i];
        float nm = fmaxf(m, x);
        s = s * __expf(m - nm) + __expf(x - nm);
        m = nm;
    }
    #pragma unroll
    for (int o = 16; o; o >>= 1) {
        float m2 = __shfl_xor_sync(0xffffffffu, m, o);
        float s2 = __shfl_xor_sync(0xffffffffu, s, o);
        float nm = fmaxf(m, m2);
        s = s * __expf(m - nm) + s2 * __expf(m2 - nm);
        m = nm;
    }
    if ((tid & 31) == 0) { sm[tid >> 5] = m; ss[tid >> 5] = s; }
    __syncthreads();
    if (tid < 8) {
        m = sm[tid]; s = ss[tid];
        #pragma unroll
        for (int o = 4; o; o >>= 1) {
            float m2 = __shfl_xor_sync(0xffu, m, o);
            float s2 = __shfl_xor_sync(0xffu, s, o);
            float nm = fmaxf(m, m2);
            s = s * __expf(m - nm) + s2 * __expf(m2 - nm);
            m = nm;
        }
        if (tid == 0) s_lse = m + logf(s);
    }
    __syncthreads();
    const float lse = s_lse;
    for (int i = tid; i < VOCAB; i += 256) p[i] -= lse;
}

// ---------------- launch ----------------
extern "C" void kernel_launch(void* const* d_in, const int* in_sizes, int n_in,
                              void* d_out, int out_size) {
    (void)in_sizes; (void)n_in; (void)out_size;
    const float* root = (const float*)d_in[0];
    const float* W1v  = (const float*)d_in[1];
    const float* b1v  = (const float*)d_in[2];
    const float* W2v  = (const float*)d_in[3];
    const float* b2v  = (const float*)d_in[4];
    const float* W1c  = (const float*)d_in[5];
    const float* b1c  = (const float*)d_in[6];
    const float* W2c  = (const float*)d_in[7];
    const float* b2c  = (const float*)d_in[8];

    void *pa;
    cudaGetSymbolAddress(&pa, g_h);   __nv_bfloat16* g_h_p   = (__nv_bfloat16*)pa;
    cudaGetSymbolAddress(&pa, g_mid); __nv_bfloat16* g_mid_p = (__nv_bfloat16*)pa;
    cudaGetSymbolAddress(&pa, g_W1c); __nv_bfloat16* W1c_b   = (__nv_bfloat16*)pa;
    cudaGetSymbolAddress(&pa, g_W2c); __nv_bfloat16* W2c_b   = (__nv_bfloat16*)pa;
    cudaGetSymbolAddress(&pa, g_W1v); __nv_bfloat16* W1v_b   = (__nv_bfloat16*)pa;
    cudaGetSymbolAddress(&pa, g_W2v); __nv_bfloat16* W2v_b   = (__nv_bfloat16*)pa;

    cvt_root_kernel<<<4, 256>>>(root);
    cvt_w_kernel<<<(H * H2 + 255) / 256, 256>>>(W1c, W1c_b, H * H2);
    cvt_w_kernel<<<(H2 * H2 + 255) / 256, 256>>>(W2c, W2c_b, H2 * H2);
    cvt_w_kernel<<<(H * H2 + 255) / 256, 256>>>(W1v, W1v_b, H * H2);
    {
        int total = H2 * VPAD;
        cvt_pad_kernel<<<(total + 255) / 256, 256>>>(W2v, W2v_b, VOCAB, VPAD, total);
    }

    // ---- tree expansion ----
    int off = 0;                                // 2^d - 1
    for (int d = 0; d < DEPTH; ++d) {
        const int R = 1 << d;
        dim3 grid((R + BM - 1) / BM, H2 / BN);
        gemm_bf16<0><<<grid, 256>>>(g_h_p + (size_t)off * H, H, W1c_b, H2, b1c,
                                    R, H2, H, g_mid_p, 0);
        gemm_bf16<1><<<grid, 256>>>(g_mid_p, H2, W2c_b, H2, b2c,
                                    R, H2, H2, nullptr, 2 * off + 1);
        off = 2 * off + 1;
    }

    // ---- vocab first layer for all nodes ----
    {
        dim3 grid((NODES + BM - 1) / BM, H2 / BN);
        gemm_bf16<0><<<grid, 256>>>(g_h_p, H, W1v_b, H2, b1v,
                                    NODES, H2, H, g_mid_p, 0);
    }

    // ---- big logits GEMM (x = M-tiles fastest for L2 reuse of B strips) ----
    {
        dim3 grid((NODES + BM - 1) / BM, VPAD / BN);
        gemm_bf16<2><<<grid, 256>>>(g_mid_p, H2, W2v_b, VPAD, b2v,
                                    NODES, VOCAB, H2, d_out, 0);
    }

    logsoftmax_kernel<<<NODES, 256>>>((float*)d_out);
}

// round 6
// speedup vs baseline: 3.1407x; 1.5595x over previous
#include <cuda_runtime.h>
#include <cuda_bf16.h>
#include <cstdint>

#define H      1024
#define H2     2048
#define VOCAB  32001
#define VPAD   32128   // 251 * 128 : padded cols of bf16 W2v
#define DEPTH  11
#define NODES  4095

// ---------------- scratch (static device globals: allowed) ----------------
__device__ __nv_bfloat16 g_h[NODES * H];                 // node hiddens, BFS order
__device__ __nv_bfloat16 g_mid[(size_t)NODES * H2];      // sigmoid activations
__device__ __nv_bfloat16 g_W1c[H * H2];
__device__ __nv_bfloat16 g_W2c[H2 * H2];
__device__ __nv_bfloat16 g_W1v[H * H2];
__device__ __nv_bfloat16 g_W2v[(size_t)H2 * VPAD];       // [k][n] bf16, cols >= 32001 zero
__device__ float         g_rowsum[NODES];                // sum(exp(logits)) per preorder row

__device__ __forceinline__ uint32_t smem_u32(const void* p) {
    return (uint32_t)__cvta_generic_to_shared(p);
}

// pre-order position of BFS node j (perfect binary tree, levels 0..DEPTH)
__device__ __forceinline__ int preorder_row(int j) {
    int t = j + 1;
    int d = 31 - __clz(t);
    int p = t - (1 << d);
    int idx = 0;
    #pragma unroll 1
    for (int k = 0; k < d; ++k) {
        int b = (p >> (d - 1 - k)) & 1;
        idx += 1 + b * ((1 << (DEPTH - k)) - 1);
    }
    return idx;
}

// ============================================================================
// Proven round-4 mma.sync GEMM (tree expansion + vocab first layer).
// MODE 0: out = bf16(sigmoid(acc+bias)) -> (bf16*)outp, ld = N
// MODE 1: child scatter -> g_h : node = child_off + 2*m + (n>>10), col = n&1023
// ============================================================================
constexpr int BM = 128;
constexpr int BN = 128;
constexpr int BK = 32;
constexpr int STAGES = 3;

template <int MODE>
__global__ void __launch_bounds__(256, 2)
gemm_bf16(const __nv_bfloat16* __restrict__ A, int lda,
          const __nv_bfloat16* __restrict__ B, int ldb,
          const float* __restrict__ bias,
          int M, int N, int K,
          void* outp, int child_off)
{
    __shared__ __align__(16) unsigned char smem[STAGES * 2 * 8192];

    const int tid  = threadIdx.x;
    const int wid  = tid >> 5;
    const int lane = tid & 31;
    const int wm   = wid & 3;
    const int wn   = wid >> 2;
    const int m0   = blockIdx.x * BM;
    const int n0   = blockIdx.y * BN;

    const uint32_t sA = smem_u32(smem);
    const uint32_t sB = sA + STAGES * 8192;

    float acc[2][8][4];
    #pragma unroll
    for (int i = 0; i < 2; ++i)
        #pragma unroll
        for (int j = 0; j < 8; ++j)
            #pragma unroll
            for (int q = 0; q < 4; ++q) acc[i][j][q] = 0.0f;

    auto load_stage = [&](int s, int k0) {
        #pragma unroll
        for (int t = 0; t < 2; ++t) {
            int q = tid + t * 256;
            int r = q >> 2, c = q & 3;
            uint32_t dst = sA + s * 8192 + r * 64 + ((c ^ ((r >> 1) & 3)) << 4);
            int gm = m0 + r;
            int sz = (gm < M) ? 16 : 0;
            if (gm >= M) gm = M - 1;
            const __nv_bfloat16* src = A + (size_t)gm * lda + k0 + c * 8;
            asm volatile("cp.async.cg.shared.global [%0], [%1], 16, %2;\n"
                         :: "r"(dst), "l"(src), "r"(sz));
        }
        #pragma unroll
        for (int t = 0; t < 2; ++t) {
            int q = tid + t * 256;
            int k = q >> 4, nc = q & 15;
            uint32_t dst = sB + s * 8192 + k * 256 + ((nc ^ (k & 7)) << 4);
            const __nv_bfloat16* src = B + (size_t)(k0 + k) * ldb + n0 + nc * 8;
            asm volatile("cp.async.cg.shared.global [%0], [%1], 16;\n"
                         :: "r"(dst), "l"(src));
        }
    };

    const int kiters = K >> 5;

    #pragma unroll
    for (int s = 0; s < STAGES - 1; ++s) {
        load_stage(s, s * BK);
        asm volatile("cp.async.commit_group;\n");
    }

    for (int it = 0; it < kiters; ++it) {
        asm volatile("cp.async.wait_group %0;\n" :: "n"(STAGES - 2));
        __syncthreads();
        {
            int pf = it + STAGES - 1;
            if (pf < kiters) load_stage(pf % STAGES, pf * BK);
            asm volatile("cp.async.commit_group;\n");
        }
        const uint32_t aBase = sA + (it % STAGES) * 8192;
        const uint32_t bBase = sB + (it % STAGES) * 8192;

        #pragma unroll
        for (int kk = 0; kk < 2; ++kk) {
            uint32_t a[2][4];
            #pragma unroll
            for (int i = 0; i < 2; ++i) {
                int r = wm * 32 + i * 16 + (lane & 15);
                int c = kk * 2 + (lane >> 4);
                uint32_t addr = aBase + r * 64 + ((c ^ ((r >> 1) & 3)) << 4);
                asm volatile("ldmatrix.sync.aligned.m8n8.x4.shared.b16 {%0,%1,%2,%3}, [%4];\n"
                             : "=r"(a[i][0]), "=r"(a[i][1]), "=r"(a[i][2]), "=r"(a[i][3])
                             : "r"(addr));
            }
            #pragma unroll
            for (int j2 = 0; j2 < 4; ++j2) {
                uint32_t b[4];
                int k  = kk * 16 + (lane & 15);
                int nc = wn * 8 + j2 * 2 + (lane >> 4);
                uint32_t addr = bBase + k * 256 + ((nc ^ (k & 7)) << 4);
                asm volatile("ldmatrix.sync.aligned.m8n8.x4.trans.shared.b16 {%0,%1,%2,%3}, [%4];\n"
                             : "=r"(b[0]), "=r"(b[1]), "=r"(b[2]), "=r"(b[3])
                             : "r"(addr));
                #pragma unroll
                for (int jj = 0; jj < 2; ++jj) {
                    int j = j2 * 2 + jj;
                    #pragma unroll
                    for (int i = 0; i < 2; ++i) {
                        asm volatile(
                            "mma.sync.aligned.m16n8k16.row.col.f32.bf16.bf16.f32 "
                            "{%0,%1,%2,%3}, {%4,%5,%6,%7}, {%8,%9}, {%0,%1,%2,%3};\n"
                            : "+f"(acc[i][j][0]), "+f"(acc[i][j][1]),
                              "+f"(acc[i][j][2]), "+f"(acc[i][j][3])
                            : "r"(a[i][0]), "r"(a[i][1]), "r"(a[i][2]), "r"(a[i][3]),
                              "r"(b[jj * 2]), "r"(b[jj * 2 + 1]));
                    }
                }
            }
        }
    }

    const int r0 = lane >> 2;
    const int cc = (lane & 3) * 2;
    #pragma unroll
    for (int i = 0; i < 2; ++i) {
        const int mbase = m0 + wm * 32 + i * 16;
        const int mA = mbase + r0;
        const int mB = mbase + r0 + 8;
        #pragma unroll
        for (int j = 0; j < 8; ++j) {
            const int n = n0 + wn * 64 + j * 8 + cc;
            float2 bb = *(const float2*)(bias + n);
            float v0 = acc[i][j][0] + bb.x, v1 = acc[i][j][1] + bb.y;
            float v2 = acc[i][j][2] + bb.x, v3 = acc[i][j][3] + bb.y;

            if (MODE == 0) {
                v0 = 1.0f / (1.0f + __expf(-v0));
                v1 = 1.0f / (1.0f + __expf(-v1));
                v2 = 1.0f / (1.0f + __expf(-v2));
                v3 = 1.0f / (1.0f + __expf(-v3));
                __nv_bfloat16* O = (__nv_bfloat16*)outp;
                if (mA < M) *(__nv_bfloat162*)(O + (size_t)mA * N + n) =
                    __nv_bfloat162(__float2bfloat16(v0), __float2bfloat16(v1));
                if (mB < M) *(__nv_bfloat162*)(O + (size_t)mB * N + n) =
                    __nv_bfloat162(__float2bfloat16(v2), __float2bfloat16(v3));
            } else {
                const int nodeb = child_off + (n >> 10);
                const int col   = n & (H - 1);
                if (mA < M) *(__nv_bfloat162*)&g_h[(size_t)(nodeb + 2 * mA) * H + col] =
                    __nv_bfloat162(__float2bfloat16(v0), __float2bfloat16(v1));
                if (mB < M) *(__nv_bfloat162*)&g_h[(size_t)(nodeb + 2 * mB) * H + col] =
                    __nv_bfloat162(__float2bfloat16(v2), __float2bfloat16(v3));
            }
        }
    }
}

// ============================================================================
// Logits GEMM: 128x128x64 tiles, 3-stage cp.async, 96KB dynamic smem,
// fused bias + preorder-row store + sum(exp) atomics.
// A = g_mid [NODES, 2048] bf16 ; B = g_W2v [2048, VPAD] bf16 (cols>=VOCAB zero)
// ============================================================================
constexpr int L_BK   = 64;
constexpr int L_AB   = BM * 128;                       // 16384 B / stage (rows of 128B)
constexpr int L_BB   = L_BK * 256;                     // 16384 B / stage (64 rows of 256B)
constexpr int L_SMEM = STAGES * (L_AB + L_BB);         // 98304

__global__ void __launch_bounds__(256, 2)
gemm_logits(const __nv_bfloat16* __restrict__ A,
            const __nv_bfloat16* __restrict__ B,
            const float* __restrict__ bias,
            float* __restrict__ out,
            float* __restrict__ rowsum)
{
    extern __shared__ __align__(16) unsigned char dsmem[];
    const int tid  = threadIdx.x;
    const int wid  = tid >> 5;
    const int lane = tid & 31;
    const int wm   = wid & 3;
    const int wn   = wid >> 2;
    const int m0   = blockIdx.x * BM;
    const int n0   = blockIdx.y * BN;
    const int M    = NODES;

    const uint32_t sA = smem_u32(dsmem);
    const uint32_t sB = sA + STAGES * L_AB;

    float acc[2][8][4];
    #pragma unroll
    for (int i = 0; i < 2; ++i)
        #pragma unroll
        for (int j = 0; j < 8; ++j)
            #pragma unroll
            for (int q = 0; q < 4; ++q) acc[i][j][q] = 0.0f;

    auto load_stage = [&](int s, int k0) {
        // A: 128 rows x 128B (8 chunks), swizzle c ^= r&7
        #pragma unroll
        for (int t = 0; t < 4; ++t) {
            int q = tid + t * 256;
            int r = q >> 3, c = q & 7;
            uint32_t dst = sA + s * L_AB + r * 128 + ((c ^ (r & 7)) << 4);
            int gm = m0 + r;
            if (gm >= M) gm = M - 1;
            const __nv_bfloat16* src = A + (size_t)gm * H2 + k0 + c * 8;
            asm volatile("cp.async.cg.shared.global [%0], [%1], 16;\n"
                         :: "r"(dst), "l"(src));
        }
        // B: 64 k-rows x 256B (16 chunks), swizzle nc ^= k&7 (padded: always in-bounds)
        #pragma unroll
        for (int t = 0; t < 4; ++t) {
            int q = tid + t * 256;
            int k = q >> 4, nc = q & 15;
            uint32_t dst = sB + s * L_BB + k * 256 + ((nc ^ (k & 7)) << 4);
            const __nv_bfloat16* src = B + (size_t)(k0 + k) * VPAD + n0 + nc * 8;
            asm volatile("cp.async.cg.shared.global [%0], [%1], 16;\n"
                         :: "r"(dst), "l"(src));
        }
    };

    const int kiters = H2 / L_BK;   // 32

    load_stage(0, 0);
    asm volatile("cp.async.commit_group;\n");
    load_stage(1, L_BK);
    asm volatile("cp.async.commit_group;\n");

    for (int it = 0; it < kiters; ++it) {
        asm volatile("cp.async.wait_group 1;\n");
        __syncthreads();
        {
            int pf = it + 2;
            if (pf < kiters) load_stage(pf % STAGES, pf * L_BK);
            asm volatile("cp.async.commit_group;\n");
        }
        const uint32_t aBase = sA + (it % STAGES) * L_AB;
        const uint32_t bBase = sB + (it % STAGES) * L_BB;

        #pragma unroll
        for (int kk = 0; kk < 4; ++kk) {           // four k16 steps per BK=64
            uint32_t a[2][4];
            #pragma unroll
            for (int i = 0; i < 2; ++i) {
                int r = wm * 32 + i * 16 + (lane & 15);
                int c = kk * 2 + (lane >> 4);
                uint32_t addr = aBase + r * 128 + ((c ^ (r & 7)) << 4);
                asm volatile("ldmatrix.sync.aligned.m8n8.x4.shared.b16 {%0,%1,%2,%3}, [%4];\n"
                             : "=r"(a[i][0]), "=r"(a[i][1]), "=r"(a[i][2]), "=r"(a[i][3])
                             : "r"(addr));
            }
            #pragma unroll
            for (int j2 = 0; j2 < 4; ++j2) {
                uint32_t b[4];
                int k  = kk * 16 + (lane & 15);
                int nc = wn * 8 + j2 * 2 + (lane >> 4);
                uint32_t addr = bBase + k * 256 + ((nc ^ (k & 7)) << 4);
                asm volatile("ldmatrix.sync.aligned.m8n8.x4.trans.shared.b16 {%0,%1,%2,%3}, [%4];\n"
                             : "=r"(b[0]), "=r"(b[1]), "=r"(b[2]), "=r"(b[3])
                             : "r"(addr));
                #pragma unroll
                for (int jj = 0; jj < 2; ++jj) {
                    int j = j2 * 2 + jj;
                    #pragma unroll
                    for (int i = 0; i < 2; ++i) {
                        asm volatile(
                            "mma.sync.aligned.m16n8k16.row.col.f32.bf16.bf16.f32 "
                            "{%0,%1,%2,%3}, {%4,%5,%6,%7}, {%8,%9}, {%0,%1,%2,%3};\n"
                            : "+f"(acc[i][j][0]), "+f"(acc[i][j][1]),
                              "+f"(acc[i][j][2]), "+f"(acc[i][j][3])
                            : "r"(a[i][0]), "r"(a[i][1]), "r"(a[i][2]), "r"(a[i][3]),
                              "r"(b[jj * 2]), "r"(b[jj * 2 + 1]));
                    }
                }
            }
        }
    }

    // ---- epilogue: bias, preorder store, fused exp-sum ----
    const int r0 = lane >> 2;
    const int cc = (lane & 3) * 2;
    #pragma unroll
    for (int i = 0; i < 2; ++i) {
        const int mbase = m0 + wm * 32 + i * 16;
        const int mA = mbase + r0;
        const int mB = mbase + r0 + 8;
        const bool vA = (mA < M), vB = (mB < M);
        const int prA = vA ? preorder_row(mA) : 0;
        const int prB = vB ? preorder_row(mB) : 0;
        float* oA = out + (size_t)prA * VOCAB;
        float* oB = out + (size_t)prB * VOCAB;
        float eA = 0.0f, eB = 0.0f;
        #pragma unroll
        for (int j = 0; j < 8; ++j) {
            const int n = n0 + wn * 64 + j * 8 + cc;
            const bool g0 = (n < VOCAB), g1 = (n + 1 < VOCAB);
            const float bv0 = g0 ? __ldg(bias + n)     : 0.0f;
            const float bv1 = g1 ? __ldg(bias + n + 1) : 0.0f;
            float v0 = acc[i][j][0] + bv0, v1 = acc[i][j][1] + bv1;
            float v2 = acc[i][j][2] + bv0, v3 = acc[i][j][3] + bv1;
            if (vA) {
                if (g0) { oA[n]     = v0; eA += __expf(v0); }
                if (g1) { oA[n + 1] = v1; eA += __expf(v1); }
            }
            if (vB) {
                if (g0) { oB[n]     = v2; eB += __expf(v2); }
                if (g1) { oB[n + 1] = v3; eB += __expf(v3); }
            }
        }
        // quad reduce over lanes sharing the same row (lane bits 0-1)
        eA += __shfl_xor_sync(0xffffffffu, eA, 1);
        eA += __shfl_xor_sync(0xffffffffu, eA, 2);
        eB += __shfl_xor_sync(0xffffffffu, eB, 1);
        eB += __shfl_xor_sync(0xffffffffu, eB, 2);
        if ((lane & 3) == 0) {
            if (vA) atomicAdd(rowsum + prA, eA);
            if (vB) atomicAdd(rowsum + prB, eB);
        }
    }
}

// ---------------- small kernels ----------------
__global__ void cvt_root_kernel(const float* __restrict__ root) {
    int i = blockIdx.x * 256 + threadIdx.x;
    if (i < H) g_h[i] = __float2bfloat16(root[i]);
    if (blockIdx.x == 0) {           // also zero the rowsum accumulators
        for (int r = threadIdx.x; r < NODES; r += 256) g_rowsum[r] = 0.0f;
    }
}

__global__ void cvt_w_kernel(const float* __restrict__ src, __nv_bfloat16* __restrict__ dst, int n) {
    int i = blockIdx.x * 256 + threadIdx.x;
    if (i < n) dst[i] = __float2bfloat16(src[i]);
}

__global__ void cvt_pad_kernel(const float* __restrict__ src, __nv_bfloat16* __restrict__ dst,
                               int nc, int ncp, int total) {
    int i = blockIdx.x * 256 + threadIdx.x;
    if (i < total) {
        int r = i / ncp, c = i - r * ncp;
        dst[i] = (c < nc) ? __float2bfloat16(src[(size_t)r * nc + c]) : __float2bfloat16(0.0f);
    }
}

// out[r][i] -= log(rowsum[r])
__global__ void __launch_bounds__(256)
lse_sub_kernel(float* __restrict__ out, const float* __restrict__ rowsum) {
    const int r = blockIdx.x;
    const float lse = logf(rowsum[r]);
    float* p = out + (size_t)r * VOCAB;
    for (int i = threadIdx.x; i < VOCAB; i += 256) p[i] -= lse;
}

// ---------------- launch ----------------
extern "C" void kernel_launch(void* const* d_in, const int* in_sizes, int n_in,
                              void* d_out, int out_size) {
    (void)in_sizes; (void)n_in; (void)out_size;
    const float* root = (const float*)d_in[0];
    const float* W1v  = (const float*)d_in[1];
    const float* b1v  = (const float*)d_in[2];
    const float* W2v  = (const float*)d_in[3];
    const float* b2v  = (const float*)d_in[4];
    const float* W1c  = (const float*)d_in[5];
    const float* b1c  = (const float*)d_in[6];
    const float* W2c  = (const float*)d_in[7];
    const float* b2c  = (const float*)d_in[8];

    void* pa;
    cudaGetSymbolAddress(&pa, g_h);      __nv_bfloat16* g_h_p    = (__nv_bfloat16*)pa;
    cudaGetSymbolAddress(&pa, g_mid);    __nv_bfloat16* g_mid_p  = (__nv_bfloat16*)pa;
    cudaGetSymbolAddress(&pa, g_W1c);    __nv_bfloat16* W1c_b    = (__nv_bfloat16*)pa;
    cudaGetSymbolAddress(&pa, g_W2c);    __nv_bfloat16* W2c_b    = (__nv_bfloat16*)pa;
    cudaGetSymbolAddress(&pa, g_W1v);    __nv_bfloat16* W1v_b    = (__nv_bfloat16*)pa;
    cudaGetSymbolAddress(&pa, g_W2v);    __nv_bfloat16* W2v_b    = (__nv_bfloat16*)pa;
    cudaGetSymbolAddress(&pa, g_rowsum); float*         rowsum_p = (float*)pa;

    cudaFuncSetAttribute(gemm_logits, cudaFuncAttributeMaxDynamicSharedMemorySize, L_SMEM);

    cvt_root_kernel<<<4, 256>>>(root);
    cvt_w_kernel<<<(H * H2 + 255) / 256, 256>>>(W1c, W1c_b, H * H2);
    cvt_w_kernel<<<(H2 * H2 + 255) / 256, 256>>>(W2c, W2c_b, H2 * H2);
    cvt_w_kernel<<<(H * H2 + 255) / 256, 256>>>(W1v, W1v_b, H * H2);
    {
        int total = H2 * VPAD;
        cvt_pad_kernel<<<(total + 255) / 256, 256>>>(W2v, W2v_b, VOCAB, VPAD, total);
    }

    // ---- tree expansion ----
    int off = 0;
    for (int d = 0; d < DEPTH; ++d) {
        const int R = 1 << d;
        dim3 grid((R + BM - 1) / BM, H2 / BN);
        gemm_bf16<0><<<grid, 256>>>(g_h_p + (size_t)off * H, H, W1c_b, H2, b1c,
                                    R, H2, H, g_mid_p, 0);
        gemm_bf16<1><<<grid, 256>>>(g_mid_p, H2, W2c_b, H2, b2c,
                                    R, H2, H2, nullptr, 2 * off + 1);
        off = 2 * off + 1;
    }

    // ---- vocab first layer for all nodes ----
    {
        dim3 grid((NODES + BM - 1) / BM, H2 / BN);
        gemm_bf16<0><<<grid, 256>>>(g_h_p, H, W1v_b, H2, b1v,
                                    NODES, H2, H, g_mid_p, 0);
    }

    // ---- logits GEMM (M-tiles fastest -> B-strip L2 reuse) ----
    {
        dim3 grid((NODES + BM - 1) / BM, VPAD / BN);
        gemm_logits<<<grid, 256, L_SMEM>>>(g_mid_p, W2v_b, b2v,
                                           (float*)d_out, rowsum_p);
    }

    // ---- final: subtract log-sum-exp ----
    lse_sub_kernel<<<NODES, 256>>>((float*)d_out, rowsum_p);
}